// round 14
// baseline (speedup 1.0000x reference)
#include <cuda_runtime.h>
#include <cstdint>

// Fused CBF-QP controller. R14 = R8 winner (f32x2 math, dual-port weights,
// hw tanh) with ONE change: __launch_bounds__(256, 4) -> <=64 regs,
// 4 blocks/SM, 32 warps (was 80 regs / 3 blocks / 24 warps). Attacks the
// ~100us exposed-latency gap above the ~250us FMA-FLOP wall.

namespace {

constexpr int S_DIM = 16;
constexpr int H_DIM = 128;
constexpr int A_DIM = 4;
constexpr float QP_EPS = 1e-8f;

using u64 = unsigned long long;

struct CB {
    ulonglong2 Wc1T[H_DIM * 4];        // [j][0..3]; Wc1T[j][k] = Wc1[k*H + j]
    ulonglong2 Wc2v[H_DIM];            // Wc2 row j (4 floats)
    ulonglong2 WfT[S_DIM * 4];         // [sp][0..3]; WfT[sp][k] = Wf[k*S + sp]
    ulonglong2 WgP[S_DIM * A_DIM * 4]; // [(sp*4+a)][0..3]: k-pair packed float2 x8
    float4 bg4[S_DIM];                 // bg as [sp][a]
    float  bf[S_DIM];
    float  bc2[A_DIM];
    float  bh2;
    float  pad[3];
};

__constant__ CB cb;
__device__   CB g_scratch;

__global__ void prep_kernel(const float* __restrict__ Wc1,
                            const float* __restrict__ Wc2,
                            const float* __restrict__ Wf,
                            const float* __restrict__ Wg,
                            const float* __restrict__ bg,
                            const float* __restrict__ bf,
                            const float* __restrict__ bc2,
                            const float* __restrict__ bh2)
{
    const int tid = blockIdx.x * blockDim.x + threadIdx.x;
    const int nthr = gridDim.x * blockDim.x;

    for (int idx = tid; idx < H_DIM * S_DIM; idx += nthr) {
        const int j = idx >> 4;
        const int k = idx & 15;
        reinterpret_cast<float*>(g_scratch.Wc1T)[j * 16 + k] = Wc1[k * H_DIM + j];
    }
    for (int idx = tid; idx < H_DIM * 4; idx += nthr) {
        reinterpret_cast<float*>(g_scratch.Wc2v)[idx] = Wc2[idx];
    }
    for (int idx = tid; idx < S_DIM * S_DIM; idx += nthr) {
        const int sp = idx >> 4;
        const int k = idx & 15;
        reinterpret_cast<float*>(g_scratch.WfT)[sp * 16 + k] = Wf[k * S_DIM + sp];
    }
    for (int idx = tid; idx < S_DIM * A_DIM * 8; idx += nthr) {
        const int spa = idx >> 3;
        const int m = idx & 7;
        const float lo = Wg[(2 * m) * (S_DIM * A_DIM) + spa];
        const float hi = Wg[(2 * m + 1) * (S_DIM * A_DIM) + spa];
        reinterpret_cast<float2*>(g_scratch.WgP)[spa * 8 + m] = make_float2(lo, hi);
    }
    for (int idx = tid; idx < S_DIM * A_DIM; idx += nthr) {
        reinterpret_cast<float*>(g_scratch.bg4)[idx] = bg[idx];
    }
    if (tid < S_DIM) g_scratch.bf[tid] = bf[tid];
    if (tid < A_DIM) g_scratch.bc2[tid] = bc2[tid];
    if (tid == 0)    g_scratch.bh2 = bh2[0];
}

__device__ __forceinline__ u64 pack2(float lo, float hi) {
    u64 r;
    asm("mov.b64 %0, {%1, %2};" : "=l"(r) : "f"(lo), "f"(hi));
    return r;
}
__device__ __forceinline__ void unpack2(u64 v, float& lo, float& hi) {
    asm("mov.b64 {%0, %1}, %2;" : "=f"(lo), "=f"(hi) : "l"(v));
}
__device__ __forceinline__ u64 fma2(u64 a, u64 b, u64 c) {
    u64 d;
    asm("fma.rn.f32x2 %0, %1, %2, %3;" : "=l"(d) : "l"(a), "l"(b), "l"(c));
    return d;
}
__device__ __forceinline__ u64 add2(u64 a, u64 b) {
    u64 d;
    asm("add.rn.f32x2 %0, %1, %2;" : "=l"(d) : "l"(a), "l"(b));
    return d;
}
__device__ __forceinline__ u64 mul2(u64 a, u64 b) {
    u64 d;
    asm("mul.rn.f32x2 %0, %1, %2;" : "=l"(d) : "l"(a), "l"(b));
    return d;
}

// Hardware tanh: single MUFU op, max rel err ~5e-4 (threshold is 1e-3).
__device__ __forceinline__ float hw_tanh(float x) {
    float y;
    asm("tanh.approx.f32 %0, %1;" : "=f"(y) : "f"(x));
    return y;
}

__device__ __forceinline__ float dot16p(const u64* s2,
                                        ulonglong2 w0, ulonglong2 w1,
                                        ulonglong2 w2, ulonglong2 w3, float bias) {
    u64 a0 = mul2(s2[0], w0.x);
    u64 a1 = mul2(s2[4], w2.x);
    a0 = fma2(s2[1], w0.y, a0);
    a1 = fma2(s2[5], w2.y, a1);
    a0 = fma2(s2[2], w1.x, a0);
    a1 = fma2(s2[6], w3.x, a1);
    a0 = fma2(s2[3], w1.y, a0);
    a1 = fma2(s2[7], w3.y, a1);
    u64 sum = add2(a0, a1);
    float lo, hi;
    unpack2(sum, lo, hi);
    return bias + lo + hi;
}

__global__ void __launch_bounds__(256, 4)
cbf_fused(const float* __restrict__ state,
          const float* __restrict__ Wh1, const float* __restrict__ bc1,
          const float* __restrict__ bh1, const float* __restrict__ wh2,
          float* __restrict__ out, int total)
{
    __shared__ float4 sWh1[H_DIM][4];   // Wh1^T (LDS port)
    __shared__ float4 sB[H_DIM];        // (bc1, bh1, wh2, 0)

    const int tid = threadIdx.x;

    for (int idx = tid; idx < H_DIM * S_DIM; idx += blockDim.x) {
        const int j = idx >> 4;
        const int k = idx & 15;
        reinterpret_cast<float*>(sWh1)[idx] = Wh1[k * H_DIM + j];
    }
    for (int j = tid; j < H_DIM; j += blockDim.x) {
        sB[j] = make_float4(bc1[j], bh1[j], wh2[j], 0.0f);
    }
    __syncthreads();

    const int row = blockIdx.x * blockDim.x + tid;
    if (row >= total) return;

    u64 s2[8];
    {
        const ulonglong2* sp2 =
            reinterpret_cast<const ulonglong2*>(state + (size_t)row * S_DIM);
        const ulonglong2 a = sp2[0];
        const ulonglong2 b = sp2[1];
        const ulonglong2 c = sp2[2];
        const ulonglong2 d = sp2[3];
        s2[0] = a.x; s2[1] = a.y;
        s2[2] = b.x; s2[3] = b.y;
        s2[4] = c.x; s2[5] = c.y;
        s2[6] = d.x; s2[7] = d.y;
    }

    u64 uu01 = 0ull;
    u64 uu23 = 0ull;
    float hval = 0.0f;
    u64 dh2[8];
    #pragma unroll
    for (int m = 0; m < 8; ++m) dh2[m] = 0ull;

    #pragma unroll 4
    for (int j = 0; j < H_DIM; ++j) {
        const float4 bias = sB[j];                         // LDS

        // controller branch: weights from constant port
        const ulonglong2 w0 = cb.Wc1T[j * 4 + 0];
        const ulonglong2 w1 = cb.Wc1T[j * 4 + 1];
        const ulonglong2 w2 = cb.Wc1T[j * 4 + 2];
        const ulonglong2 w3 = cb.Wc1T[j * 4 + 3];
        const float t1 = hw_tanh(dot16p(s2, w0, w1, w2, w3, bias.x));
        const u64 t1p = pack2(t1, t1);
        const ulonglong2 wv2 = cb.Wc2v[j];
        uu01 = fma2(t1p, wv2.x, uu01);
        uu23 = fma2(t1p, wv2.y, uu23);

        // CBF branch: weights from shared port
        const ulonglong2* wh = reinterpret_cast<const ulonglong2*>(&sWh1[j][0]);
        const ulonglong2 h0 = wh[0];
        const ulonglong2 h1 = wh[1];
        const ulonglong2 h2 = wh[2];
        const ulonglong2 h3 = wh[3];
        const float t2 = hw_tanh(dot16p(s2, h0, h1, h2, h3, bias.y));
        hval = fmaf(t2, bias.z, hval);
        const float cj = fmaf(-t2 * t2, bias.z, bias.z);   // (1 - t2^2) * wh2[j]
        const u64 cj2 = pack2(cj, cj);
        dh2[0] = fma2(cj2, h0.x, dh2[0]);
        dh2[1] = fma2(cj2, h0.y, dh2[1]);
        dh2[2] = fma2(cj2, h1.x, dh2[2]);
        dh2[3] = fma2(cj2, h1.y, dh2[3]);
        dh2[4] = fma2(cj2, h2.x, dh2[4]);
        dh2[5] = fma2(cj2, h2.y, dh2[5]);
        dh2[6] = fma2(cj2, h3.x, dh2[6]);
        dh2[7] = fma2(cj2, h3.y, dh2[7]);
    }

    float dh[16];
    #pragma unroll
    for (int m = 0; m < 8; ++m) {
        unpack2(dh2[m], dh[2 * m], dh[2 * m + 1]);
    }

    // right = h + dh . f   (Wf from constant)
    float right = hval + cb.bh2;
    #pragma unroll
    for (int sp = 0; sp < S_DIM; ++sp) {
        const ulonglong2 f0 = cb.WfT[sp * 4 + 0];
        const ulonglong2 f1 = cb.WfT[sp * 4 + 1];
        const ulonglong2 f2 = cb.WfT[sp * 4 + 2];
        const ulonglong2 f3 = cb.WfT[sp * 4 + 3];
        right = fmaf(dh[sp], dot16p(s2, f0, f1, f2, f3, cb.bf[sp]), right);
    }

    // L[a] = sum_sp dh[sp] * g[sp][a]   (Wg from constant; left = -L)
    float L[4] = {0.f, 0.f, 0.f, 0.f};
    #pragma unroll
    for (int sp = 0; sp < S_DIM; ++sp) {
        const float4 bgv = cb.bg4[sp];
        const float bgarr[4] = {bgv.x, bgv.y, bgv.z, bgv.w};
        const float d = dh[sp];
        #pragma unroll
        for (int a = 0; a < A_DIM; ++a) {
            const int spa = sp * 4 + a;
            const ulonglong2 p0 = cb.WgP[spa * 4 + 0];
            const ulonglong2 p1 = cb.WgP[spa * 4 + 1];
            const ulonglong2 p2 = cb.WgP[spa * 4 + 2];
            const ulonglong2 p3 = cb.WgP[spa * 4 + 3];
            u64 acc = mul2(s2[0], p0.x);
            acc = fma2(s2[1], p0.y, acc);
            acc = fma2(s2[2], p1.x, acc);
            acc = fma2(s2[3], p1.y, acc);
            acc = fma2(s2[4], p2.x, acc);
            acc = fma2(s2[5], p2.y, acc);
            acc = fma2(s2[6], p3.x, acc);
            acc = fma2(s2[7], p3.y, acc);
            float lo, hi;
            unpack2(acc, lo, hi);
            L[a] = fmaf(d, lo + hi + bgarr[a], L[a]);
        }
    }

    // QP epilogue: u_unc = 2*(t1@Wc2 + bc2); viol = -L.u - right; u = u_unc + lam*L
    float uu0, uu1, uu2, uu3;
    unpack2(uu01, uu0, uu1);
    unpack2(uu23, uu2, uu3);
    const float u0 = 2.0f * (uu0 + cb.bc2[0]);
    const float u1 = 2.0f * (uu1 + cb.bc2[1]);
    const float u2 = 2.0f * (uu2 + cb.bc2[2]);
    const float u3 = 2.0f * (uu3 + cb.bc2[3]);

    const float viol = -(L[0] * u0 + L[1] * u1 + L[2] * u2 + L[3] * u3) - right;
    const float den  = L[0] * L[0] + L[1] * L[1] + L[2] * L[2] + L[3] * L[3] + QP_EPS;
    const float lam  = viol > 0.0f ? (viol / den) : 0.0f;

    float4 res;
    res.x = fmaf(lam, L[0], u0);
    res.y = fmaf(lam, L[1], u1);
    res.z = fmaf(lam, L[2], u2);
    res.w = fmaf(lam, L[3], u3);
    reinterpret_cast<float4*>(out)[row] = res;
}

} // namespace

extern "C" void kernel_launch(void* const* d_in, const int* in_sizes, int n_in,
                              void* d_out, int out_size) {
    const float* state = (const float*)d_in[0];
    const float* Wc1   = (const float*)d_in[1];
    const float* bc1   = (const float*)d_in[2];
    const float* Wc2   = (const float*)d_in[3];
    const float* bc2   = (const float*)d_in[4];
    const float* Wh1   = (const float*)d_in[5];
    const float* bh1   = (const float*)d_in[6];
    const float* wh2   = (const float*)d_in[7];
    const float* bh2   = (const float*)d_in[8];
    const float* Wf    = (const float*)d_in[9];
    const float* bf    = (const float*)d_in[10];
    const float* Wg    = (const float*)d_in[11];
    const float* bg    = (const float*)d_in[12];

    // 1) pack/transpose weights into device scratch
    prep_kernel<<<16, 256>>>(Wc1, Wc2, Wf, Wg, bg, bf, bc2, bh2);

    // 2) scratch -> constant bank (D2D async memcpy, graph-capturable)
    void* scratch_ptr = nullptr;
    void* cb_ptr = nullptr;
    cudaGetSymbolAddress(&scratch_ptr, g_scratch);
    cudaGetSymbolAddress(&cb_ptr, cb);
    cudaMemcpyAsync(cb_ptr, scratch_ptr, sizeof(CB), cudaMemcpyDeviceToDevice, 0);

    // 3) main kernel
    const int total = in_sizes[0] / 16;   // B*T rows
    const int threads = 256;
    const int blocks = (total + threads - 1) / threads;
    cbf_fused<<<blocks, threads>>>(state, Wh1, bc1, bh1, wh2, (float*)d_out, total);
}

// round 15
// speedup vs baseline: 1.1060x; 1.1060x over previous
#include <cuda_runtime.h>
#include <cstdint>

// Fused CBF-QP controller. R15 = R8 dual-port scheme, TWO rows per thread:
// every LDC/LDS weight load feeds two rows (halves load-issue slots/row) and
// each thread carries two independent dependency chains (in-thread ILP
// replaces the warp-level parallelism lost at 2 blocks/SM).
// Register budget: ~42 persistent/row in R8 -> ~112 est. here, under the
// 128-reg cap of __launch_bounds__(256,2). (R4's failure was ~150 vs 128.)

namespace {

constexpr int S_DIM = 16;
constexpr int H_DIM = 128;
constexpr int A_DIM = 4;
constexpr float QP_EPS = 1e-8f;

using u64 = unsigned long long;

struct CB {
    ulonglong2 Wc1T[H_DIM * 4];        // [j][0..3]; Wc1T[j][k] = Wc1[k*H + j]
    ulonglong2 Wc2v[H_DIM];            // Wc2 row j (4 floats)
    ulonglong2 WfT[S_DIM * 4];         // [sp][0..3]; WfT[sp][k] = Wf[k*S + sp]
    ulonglong2 WgP[S_DIM * A_DIM * 4]; // [(sp*4+a)][0..3]: k-pair packed float2 x8
    float4 bg4[S_DIM];                 // bg as [sp][a]
    float  bf[S_DIM];
    float  bc2[A_DIM];
    float  bh2;
    float  pad[3];
};

__constant__ CB cb;
__device__   CB g_scratch;

__global__ void prep_kernel(const float* __restrict__ Wc1,
                            const float* __restrict__ Wc2,
                            const float* __restrict__ Wf,
                            const float* __restrict__ Wg,
                            const float* __restrict__ bg,
                            const float* __restrict__ bf,
                            const float* __restrict__ bc2,
                            const float* __restrict__ bh2)
{
    const int tid = blockIdx.x * blockDim.x + threadIdx.x;
    const int nthr = gridDim.x * blockDim.x;

    for (int idx = tid; idx < H_DIM * S_DIM; idx += nthr) {
        const int j = idx >> 4;
        const int k = idx & 15;
        reinterpret_cast<float*>(g_scratch.Wc1T)[j * 16 + k] = Wc1[k * H_DIM + j];
    }
    for (int idx = tid; idx < H_DIM * 4; idx += nthr) {
        reinterpret_cast<float*>(g_scratch.Wc2v)[idx] = Wc2[idx];
    }
    for (int idx = tid; idx < S_DIM * S_DIM; idx += nthr) {
        const int sp = idx >> 4;
        const int k = idx & 15;
        reinterpret_cast<float*>(g_scratch.WfT)[sp * 16 + k] = Wf[k * S_DIM + sp];
    }
    for (int idx = tid; idx < S_DIM * A_DIM * 8; idx += nthr) {
        const int spa = idx >> 3;
        const int m = idx & 7;
        const float lo = Wg[(2 * m) * (S_DIM * A_DIM) + spa];
        const float hi = Wg[(2 * m + 1) * (S_DIM * A_DIM) + spa];
        reinterpret_cast<float2*>(g_scratch.WgP)[spa * 8 + m] = make_float2(lo, hi);
    }
    for (int idx = tid; idx < S_DIM * A_DIM; idx += nthr) {
        reinterpret_cast<float*>(g_scratch.bg4)[idx] = bg[idx];
    }
    if (tid < S_DIM) g_scratch.bf[tid] = bf[tid];
    if (tid < A_DIM) g_scratch.bc2[tid] = bc2[tid];
    if (tid == 0)    g_scratch.bh2 = bh2[0];
}

__device__ __forceinline__ u64 pack2(float lo, float hi) {
    u64 r;
    asm("mov.b64 %0, {%1, %2};" : "=l"(r) : "f"(lo), "f"(hi));
    return r;
}
__device__ __forceinline__ void unpack2(u64 v, float& lo, float& hi) {
    asm("mov.b64 {%0, %1}, %2;" : "=f"(lo), "=f"(hi) : "l"(v));
}
__device__ __forceinline__ u64 fma2(u64 a, u64 b, u64 c) {
    u64 d;
    asm("fma.rn.f32x2 %0, %1, %2, %3;" : "=l"(d) : "l"(a), "l"(b), "l"(c));
    return d;
}
__device__ __forceinline__ u64 add2(u64 a, u64 b) {
    u64 d;
    asm("add.rn.f32x2 %0, %1, %2;" : "=l"(d) : "l"(a), "l"(b));
    return d;
}
__device__ __forceinline__ u64 mul2(u64 a, u64 b) {
    u64 d;
    asm("mul.rn.f32x2 %0, %1, %2;" : "=l"(d) : "l"(a), "l"(b));
    return d;
}

// Hardware tanh: single MUFU op, max rel err ~5e-4 (threshold is 1e-3).
__device__ __forceinline__ float hw_tanh(float x) {
    float y;
    asm("tanh.approx.f32 %0, %1;" : "=f"(y) : "f"(x));
    return y;
}

__device__ __forceinline__ float dot16p(const u64* s2,
                                        ulonglong2 w0, ulonglong2 w1,
                                        ulonglong2 w2, ulonglong2 w3, float bias) {
    u64 a0 = mul2(s2[0], w0.x);
    u64 a1 = mul2(s2[4], w2.x);
    a0 = fma2(s2[1], w0.y, a0);
    a1 = fma2(s2[5], w2.y, a1);
    a0 = fma2(s2[2], w1.x, a0);
    a1 = fma2(s2[6], w3.x, a1);
    a0 = fma2(s2[3], w1.y, a0);
    a1 = fma2(s2[7], w3.y, a1);
    u64 sum = add2(a0, a1);
    float lo, hi;
    unpack2(sum, lo, hi);
    return bias + lo + hi;
}

__global__ void __launch_bounds__(256, 2)
cbf_fused(const float* __restrict__ state,
          const float* __restrict__ Wh1, const float* __restrict__ bc1,
          const float* __restrict__ bh1, const float* __restrict__ wh2,
          float* __restrict__ out, int total)
{
    __shared__ float4 sWh1[H_DIM][4];   // Wh1^T (LDS port)
    __shared__ float4 sB[H_DIM];        // (bc1, bh1, wh2, 0)

    const int tid = threadIdx.x;

    for (int idx = tid; idx < H_DIM * S_DIM; idx += blockDim.x) {
        const int j = idx >> 4;
        const int k = idx & 15;
        reinterpret_cast<float*>(sWh1)[idx] = Wh1[k * H_DIM + j];
    }
    for (int j = tid; j < H_DIM; j += blockDim.x) {
        sB[j] = make_float4(bc1[j], bh1[j], wh2[j], 0.0f);
    }
    __syncthreads();

    const int t = blockIdx.x * blockDim.x + tid;
    const int rowA = 2 * t;
    if (rowA >= total) return;
    const int rowB = rowA + 1;
    const bool hasB = (rowB < total);

    u64 sA[8];
    u64 sBv[8];
    {
        const ulonglong2* pa =
            reinterpret_cast<const ulonglong2*>(state + (size_t)rowA * S_DIM);
        const ulonglong2 a0 = pa[0];
        const ulonglong2 a1 = pa[1];
        const ulonglong2 a2 = pa[2];
        const ulonglong2 a3 = pa[3];
        sA[0] = a0.x; sA[1] = a0.y;
        sA[2] = a1.x; sA[3] = a1.y;
        sA[4] = a2.x; sA[5] = a2.y;
        sA[6] = a3.x; sA[7] = a3.y;
        const size_t rB = hasB ? (size_t)rowB : (size_t)rowA;
        const ulonglong2* pb =
            reinterpret_cast<const ulonglong2*>(state + rB * S_DIM);
        const ulonglong2 b0 = pb[0];
        const ulonglong2 b1 = pb[1];
        const ulonglong2 b2 = pb[2];
        const ulonglong2 b3 = pb[3];
        sBv[0] = b0.x; sBv[1] = b0.y;
        sBv[2] = b1.x; sBv[3] = b1.y;
        sBv[4] = b2.x; sBv[5] = b2.y;
        sBv[6] = b3.x; sBv[7] = b3.y;
    }

    u64 uuA01 = 0ull;
    u64 uuA23 = 0ull;
    u64 uuB01 = 0ull;
    u64 uuB23 = 0ull;
    float hvalA = 0.0f;
    float hvalB = 0.0f;
    u64 dhA[8];
    u64 dhB[8];
    #pragma unroll
    for (int m = 0; m < 8; ++m) {
        dhA[m] = 0ull;
        dhB[m] = 0ull;
    }

    #pragma unroll 2
    for (int j = 0; j < H_DIM; ++j) {
        const float4 bias = sB[j];                         // LDS

        // controller branch: weights from constant port (shared by both rows)
        const ulonglong2 w0 = cb.Wc1T[j * 4 + 0];
        const ulonglong2 w1 = cb.Wc1T[j * 4 + 1];
        const ulonglong2 w2 = cb.Wc1T[j * 4 + 2];
        const ulonglong2 w3 = cb.Wc1T[j * 4 + 3];
        const float t1a = hw_tanh(dot16p(sA, w0, w1, w2, w3, bias.x));
        const float t1b = hw_tanh(dot16p(sBv, w0, w1, w2, w3, bias.x));
        const ulonglong2 wv2 = cb.Wc2v[j];
        const u64 t1ap = pack2(t1a, t1a);
        const u64 t1bp = pack2(t1b, t1b);
        uuA01 = fma2(t1ap, wv2.x, uuA01);
        uuA23 = fma2(t1ap, wv2.y, uuA23);
        uuB01 = fma2(t1bp, wv2.x, uuB01);
        uuB23 = fma2(t1bp, wv2.y, uuB23);

        // CBF branch: weights from shared port (shared by both rows)
        const ulonglong2* wh = reinterpret_cast<const ulonglong2*>(&sWh1[j][0]);
        const ulonglong2 h0 = wh[0];
        const ulonglong2 h1 = wh[1];
        const ulonglong2 h2 = wh[2];
        const ulonglong2 h3 = wh[3];
        const float t2a = hw_tanh(dot16p(sA, h0, h1, h2, h3, bias.y));
        const float t2b = hw_tanh(dot16p(sBv, h0, h1, h2, h3, bias.y));
        hvalA = fmaf(t2a, bias.z, hvalA);
        hvalB = fmaf(t2b, bias.z, hvalB);
        const float cja = fmaf(-t2a * t2a, bias.z, bias.z);
        const float cjb = fmaf(-t2b * t2b, bias.z, bias.z);
        const u64 cA = pack2(cja, cja);
        const u64 cB = pack2(cjb, cjb);
        dhA[0] = fma2(cA, h0.x, dhA[0]);
        dhA[1] = fma2(cA, h0.y, dhA[1]);
        dhA[2] = fma2(cA, h1.x, dhA[2]);
        dhA[3] = fma2(cA, h1.y, dhA[3]);
        dhA[4] = fma2(cA, h2.x, dhA[4]);
        dhA[5] = fma2(cA, h2.y, dhA[5]);
        dhA[6] = fma2(cA, h3.x, dhA[6]);
        dhA[7] = fma2(cA, h3.y, dhA[7]);
        dhB[0] = fma2(cB, h0.x, dhB[0]);
        dhB[1] = fma2(cB, h0.y, dhB[1]);
        dhB[2] = fma2(cB, h1.x, dhB[2]);
        dhB[3] = fma2(cB, h1.y, dhB[3]);
        dhB[4] = fma2(cB, h2.x, dhB[4]);
        dhB[5] = fma2(cB, h2.y, dhB[5]);
        dhB[6] = fma2(cB, h3.x, dhB[6]);
        dhB[7] = fma2(cB, h3.y, dhB[7]);
    }

    float dA[16];
    float dB[16];
    #pragma unroll
    for (int m = 0; m < 8; ++m) {
        unpack2(dhA[m], dA[2 * m], dA[2 * m + 1]);
        unpack2(dhB[m], dB[2 * m], dB[2 * m + 1]);
    }

    // right = h + dh . f   (Wf from constant, shared by both rows)
    float rightA = hvalA + cb.bh2;
    float rightB = hvalB + cb.bh2;
    #pragma unroll
    for (int sp = 0; sp < S_DIM; ++sp) {
        const ulonglong2 f0 = cb.WfT[sp * 4 + 0];
        const ulonglong2 f1 = cb.WfT[sp * 4 + 1];
        const ulonglong2 f2 = cb.WfT[sp * 4 + 2];
        const ulonglong2 f3 = cb.WfT[sp * 4 + 3];
        const float bfv = cb.bf[sp];
        rightA = fmaf(dA[sp], dot16p(sA, f0, f1, f2, f3, bfv), rightA);
        rightB = fmaf(dB[sp], dot16p(sBv, f0, f1, f2, f3, bfv), rightB);
    }

    // L[a] = sum_sp dh[sp] * g[sp][a]   (Wg from constant, shared; left = -L)
    float LA[4] = {0.f, 0.f, 0.f, 0.f};
    float LB[4] = {0.f, 0.f, 0.f, 0.f};
    #pragma unroll
    for (int sp = 0; sp < S_DIM; ++sp) {
        const float4 bgv = cb.bg4[sp];
        const float bgarr[4] = {bgv.x, bgv.y, bgv.z, bgv.w};
        const float da = dA[sp];
        const float db = dB[sp];
        #pragma unroll
        for (int a = 0; a < A_DIM; ++a) {
            const int spa = sp * 4 + a;
            const ulonglong2 p0 = cb.WgP[spa * 4 + 0];
            const ulonglong2 p1 = cb.WgP[spa * 4 + 1];
            const ulonglong2 p2 = cb.WgP[spa * 4 + 2];
            const ulonglong2 p3 = cb.WgP[spa * 4 + 3];
            u64 accA = mul2(sA[0], p0.x);
            u64 accB = mul2(sBv[0], p0.x);
            accA = fma2(sA[1], p0.y, accA);
            accB = fma2(sBv[1], p0.y, accB);
            accA = fma2(sA[2], p1.x, accA);
            accB = fma2(sBv[2], p1.x, accB);
            accA = fma2(sA[3], p1.y, accA);
            accB = fma2(sBv[3], p1.y, accB);
            accA = fma2(sA[4], p2.x, accA);
            accB = fma2(sBv[4], p2.x, accB);
            accA = fma2(sA[5], p2.y, accA);
            accB = fma2(sBv[5], p2.y, accB);
            accA = fma2(sA[6], p3.x, accA);
            accB = fma2(sBv[6], p3.x, accB);
            accA = fma2(sA[7], p3.y, accA);
            accB = fma2(sBv[7], p3.y, accB);
            float alo, ahi, blo, bhi;
            unpack2(accA, alo, ahi);
            unpack2(accB, blo, bhi);
            LA[a] = fmaf(da, alo + ahi + bgarr[a], LA[a]);
            LB[a] = fmaf(db, blo + bhi + bgarr[a], LB[a]);
        }
    }

    // QP epilogue per row
    {
        float uu0, uu1, uu2, uu3;
        unpack2(uuA01, uu0, uu1);
        unpack2(uuA23, uu2, uu3);
        const float u0 = 2.0f * (uu0 + cb.bc2[0]);
        const float u1 = 2.0f * (uu1 + cb.bc2[1]);
        const float u2 = 2.0f * (uu2 + cb.bc2[2]);
        const float u3 = 2.0f * (uu3 + cb.bc2[3]);
        const float viol = -(LA[0] * u0 + LA[1] * u1 + LA[2] * u2 + LA[3] * u3) - rightA;
        const float den  = LA[0] * LA[0] + LA[1] * LA[1] + LA[2] * LA[2] + LA[3] * LA[3] + QP_EPS;
        const float lam  = viol > 0.0f ? (viol / den) : 0.0f;
        float4 res;
        res.x = fmaf(lam, LA[0], u0);
        res.y = fmaf(lam, LA[1], u1);
        res.z = fmaf(lam, LA[2], u2);
        res.w = fmaf(lam, LA[3], u3);
        reinterpret_cast<float4*>(out)[rowA] = res;
    }
    if (hasB) {
        float uu0, uu1, uu2, uu3;
        unpack2(uuB01, uu0, uu1);
        unpack2(uuB23, uu2, uu3);
        const float u0 = 2.0f * (uu0 + cb.bc2[0]);
        const float u1 = 2.0f * (uu1 + cb.bc2[1]);
        const float u2 = 2.0f * (uu2 + cb.bc2[2]);
        const float u3 = 2.0f * (uu3 + cb.bc2[3]);
        const float viol = -(LB[0] * u0 + LB[1] * u1 + LB[2] * u2 + LB[3] * u3) - rightB;
        const float den  = LB[0] * LB[0] + LB[1] * LB[1] + LB[2] * LB[2] + LB[3] * LB[3] + QP_EPS;
        const float lam  = viol > 0.0f ? (viol / den) : 0.0f;
        float4 res;
        res.x = fmaf(lam, LB[0], u0);
        res.y = fmaf(lam, LB[1], u1);
        res.z = fmaf(lam, LB[2], u2);
        res.w = fmaf(lam, LB[3], u3);
        reinterpret_cast<float4*>(out)[rowB] = res;
    }
}

} // namespace

extern "C" void kernel_launch(void* const* d_in, const int* in_sizes, int n_in,
                              void* d_out, int out_size) {
    const float* state = (const float*)d_in[0];
    const float* Wc1   = (const float*)d_in[1];
    const float* bc1   = (const float*)d_in[2];
    const float* Wc2   = (const float*)d_in[3];
    const float* bc2   = (const float*)d_in[4];
    const float* Wh1   = (const float*)d_in[5];
    const float* bh1   = (const float*)d_in[6];
    const float* wh2   = (const float*)d_in[7];
    const float* bh2   = (const float*)d_in[8];
    const float* Wf    = (const float*)d_in[9];
    const float* bf    = (const float*)d_in[10];
    const float* Wg    = (const float*)d_in[11];
    const float* bg    = (const float*)d_in[12];

    // 1) pack/transpose weights into device scratch
    prep_kernel<<<16, 256>>>(Wc1, Wc2, Wf, Wg, bg, bf, bc2, bh2);

    // 2) scratch -> constant bank (D2D async memcpy, graph-capturable)
    void* scratch_ptr = nullptr;
    void* cb_ptr = nullptr;
    cudaGetSymbolAddress(&scratch_ptr, g_scratch);
    cudaGetSymbolAddress(&cb_ptr, cb);
    cudaMemcpyAsync(cb_ptr, scratch_ptr, sizeof(CB), cudaMemcpyDeviceToDevice, 0);

    // 3) main kernel: 2 rows per thread
    const int total = in_sizes[0] / 16;   // B*T rows
    const int threads = 256;
    const int rows_per_block = threads * 2;
    const int blocks = (total + rows_per_block - 1) / rows_per_block;
    cbf_fused<<<blocks, threads>>>(state, Wh1, bc1, bh1, wh2, (float*)d_out, total);
}